// round 2
// baseline (speedup 1.0000x reference)
#include <cuda_runtime.h>

// Problem constants (fixed shapes from reference):
//   tiles: (154, 7, 28, 16, 16, 16) fp32
//   occupancy: (8,8,8) bool
//   output: (7, 1, 28, 64, 64, 64) fp32, window SL=(8,72) -> offset 8, 5x5x5 tile corner
#define T_GRID 8
#define NT 5
#define OFF 8
#define JC 196              // 7*28
#define TILE_STRIDE 4096    // 16*16*16 floats per (tile, j, c) slab
#define N_FLOAT4 12845056   // 196 * 64*64*64 / 4

__device__ int g_lut[NT * NT * NT];

// Single-block kernel: decode occupancy (robust to bool-byte / int32 / float32
// storage), inclusive prefix sum over the 512 flat cells, emit 5x5x5 LUT of
// tile indices (-1 == unoccupied).
__global__ void build_lut_kernel(const unsigned char* __restrict__ occ_raw) {
    __shared__ int s[512];
    __shared__ int enc_bytes;
    const int t = threadIdx.x;

    const int b = occ_raw[t];          // safe: buffer is >= 512 bytes in all encodings
    s[t] = b;
    __syncthreads();
    // reduce byte-sum
    for (int off = 256; off > 0; off >>= 1) {
        if (t < off) s[t] += s[t + off];
        __syncthreads();
    }
    if (t == 0) {
        // byte-bool: sum == #occupied (154 > 128). Widened (int32/float32):
        // first 512 bytes cover 128 cells -> sum <= 128.
        enc_bytes = (s[0] > 128) ? 1 : 0;
    }
    __syncthreads();

    int v;
    if (enc_bytes) {
        v = (b != 0) ? 1 : 0;
    } else {
        // 32-bit elements: nonzero word == occupied (handles int32 and float32)
        v = (reinterpret_cast<const unsigned int*>(occ_raw)[t] != 0u) ? 1 : 0;
    }

    // inclusive prefix sum (Hillis-Steele over 512)
    s[t] = v;
    __syncthreads();
    for (int off = 1; off < 512; off <<= 1) {
        int add = (t >= off) ? s[t - off] : 0;
        __syncthreads();
        s[t] += add;
        __syncthreads();
    }
    const int idx = s[t] - 1;

    const int tx = t >> 6;
    const int ty = (t >> 3) & 7;
    const int tz = t & 7;
    if (tx < NT && ty < NT && tz < NT) {
        g_lut[(tx * NT + ty) * NT + tz] = v ? idx : -1;
    }
}

// Main gather: one float4 of output per thread. Stores fully coalesced;
// loads are aligned float4 within a single tile (offset-8 window keeps tile-z
// boundaries on float4 boundaries).
__global__ void __launch_bounds__(256) gather_kernel(
    const float* __restrict__ tiles, float4* __restrict__ out) {
    const int id = blockIdx.x * 256 + threadIdx.x;   // < 12,845,056

    int zi = id & 15;            // which float4 along z (z = 4*zi)
    int tmp = id >> 4;
    const int y = tmp & 63;  tmp >>= 6;
    const int x = tmp & 63;  tmp >>= 6;
    const int jc = tmp;          // 0..195 (j*28 + c)

    const int gz = (zi << 2) + OFF;
    const int gy = y + OFF;
    const int gx = x + OFF;
    const int tz = gz >> 4, iz = gz & 15;
    const int ty = gy >> 4, iy = gy & 15;
    const int tx = gx >> 4, ix = gx & 15;

    const int tidx = g_lut[(tx * NT + ty) * NT + tz];

    float4 v = make_float4(0.f, 0.f, 0.f, 0.f);
    if (tidx >= 0) {
        const float* src = tiles + (size_t)(tidx * JC + jc) * TILE_STRIDE
                                 + (ix << 8) + (iy << 4) + iz;
        v = *reinterpret_cast<const float4*>(src);
    }
    out[id] = v;
}

extern "C" void kernel_launch(void* const* d_in, const int* in_sizes, int n_in,
                              void* d_out, int out_size) {
    const float* tiles = (const float*)d_in[0];
    const unsigned char* occ = (const unsigned char*)d_in[1];

    build_lut_kernel<<<1, 512>>>(occ);
    gather_kernel<<<N_FLOAT4 / 256, 256>>>(tiles, (float4*)d_out);
}

// round 4
// speedup vs baseline: 1.2858x; 1.2858x over previous
#include <cuda_runtime.h>

// tiles: (154, 7, 28, 16, 16, 16) fp32
// occupancy: (8,8,8) bool (encoding auto-detected)
// output: (7, 1, 28, 64, 64, 64) fp32 == (196, 64, 64, 64), window offset 8, 5x5x5 tiles
#define NT 5
#define OFF 8
#define JC 196
#define JC_GRP 49            // 196 / 4 jc's per thread
#define TILE_STRIDE 4096     // 16^3 floats per (tile,jc) slab
#define OUT_JC_F4 65536      // 64*64*64/4 float4 per jc
#define N_THREADS (JC_GRP * OUT_JC_F4)   // 3,211,264

__device__ int g_lut[NT * NT * NT];

__global__ void build_lut_kernel(const unsigned char* __restrict__ occ_raw) {
    __shared__ int s[512];
    __shared__ int enc_bytes;
    const int t = threadIdx.x;

    const int b = occ_raw[t];
    s[t] = b;
    __syncthreads();
    for (int off = 256; off > 0; off >>= 1) {
        if (t < off) s[t] += s[t + off];
        __syncthreads();
    }
    if (t == 0) enc_bytes = (s[0] > 128) ? 1 : 0;   // byte-bool sum==154; widened <=128
    __syncthreads();

    int v;
    if (enc_bytes) {
        v = (b != 0) ? 1 : 0;
    } else {
        v = (reinterpret_cast<const unsigned int*>(occ_raw)[t] != 0u) ? 1 : 0;
    }

    s[t] = v;
    __syncthreads();
    for (int off = 1; off < 512; off <<= 1) {
        int add = (t >= off) ? s[t - off] : 0;
        __syncthreads();
        s[t] += add;
        __syncthreads();
    }
    const int idx = s[t] - 1;

    const int tx = t >> 6;
    const int ty = (t >> 3) & 7;
    const int tz = t & 7;
    if (tx < NT && ty < NT && tz < NT)
        g_lut[(tx * NT + ty) * NT + tz] = v ? idx : -1;
}

// Each thread: one spatial float4 cell, 4 jc channels (jc = grp + 49*k).
// One LUT lookup, 4 independent LDG.128 (MLP=4), 4 streaming STG.128.
__global__ void __launch_bounds__(256) gather_kernel(
    const float* __restrict__ tiles, float4* __restrict__ out) {
    const int id = blockIdx.x * 256 + threadIdx.x;   // < 3,211,264

    const int zi = id & 15;
    int tmp = id >> 4;
    const int y = tmp & 63;  tmp >>= 6;
    const int x = tmp & 63;  tmp >>= 6;
    const int grp = tmp;                 // 0..48

    const int gz = (zi << 2) + OFF;
    const int gy = y + OFF;
    const int gx = x + OFF;
    const int tz = gz >> 4, iz = gz & 15;
    const int ty = gy >> 4, iy = gy & 15;
    const int tx = gx >> 4, ix = gx & 15;

    const int tidx = g_lut[(tx * NT + ty) * NT + tz];
    const int spatial_src = (ix << 8) + (iy << 4) + iz;        // within-slab float offset
    const int spatial_out = (x << 10) + (y << 4) + zi;         // within-jc float4 offset

    float4 v0 = make_float4(0.f, 0.f, 0.f, 0.f);
    float4 v1 = v0, v2 = v0, v3 = v0;

    if (tidx >= 0) {
        const float* base = tiles + (size_t)(tidx * JC + grp) * TILE_STRIDE + spatial_src;
        v0 = *reinterpret_cast<const float4*>(base);
        v1 = *reinterpret_cast<const float4*>(base + (size_t)JC_GRP * 1 * TILE_STRIDE);
        v2 = *reinterpret_cast<const float4*>(base + (size_t)JC_GRP * 2 * TILE_STRIDE);
        v3 = *reinterpret_cast<const float4*>(base + (size_t)JC_GRP * 3 * TILE_STRIDE);
    }

    float4* o = out + spatial_out + (size_t)grp * OUT_JC_F4;
    __stcs(o,                          v0);
    __stcs(o + (size_t)1 * JC_GRP * OUT_JC_F4, v1);
    __stcs(o + (size_t)2 * JC_GRP * OUT_JC_F4, v2);
    __stcs(o + (size_t)3 * JC_GRP * OUT_JC_F4, v3);
}

extern "C" void kernel_launch(void* const* d_in, const int* in_sizes, int n_in,
                              void* d_out, int out_size) {
    const float* tiles = (const float*)d_in[0];
    const unsigned char* occ = (const unsigned char*)d_in[1];

    build_lut_kernel<<<1, 512>>>(occ);
    gather_kernel<<<N_THREADS / 256, 256>>>(tiles, (float4*)d_out);
}